// round 7
// baseline (speedup 1.0000x reference)
#include <cuda_runtime.h>
#include <cstdint>

#define D 300
#define L 128
#define LT 124
#define KW 5

#define GSTR 316
#define BSTR 152
#define BCHUNK (16*BSTR*4)                 // 9728 B
#define OFF_G   512
#define OFF_B   (OFF_G + 132*GSTR*4)       // 167360
#define OFF_RED (OFF_B + 4*BCHUNK)         // 206272
#define SMEM_T  (OFF_RED + 8*152*4)        // 211136

__device__ float d_cwT[KW*D*D];
__device__ float d_Wf[KW*D*D];
__device__ float d_biasf[D];
__device__ float d_Wpk[KW*2*304*152];      // tf32 bits, [k][oph][d 304][o' 152]
__device__ float d_conc[1024*600];

// ---------------- helpers ----------------
__device__ __forceinline__ uint32_t s2u(const void* p){
    uint32_t a; asm("{ .reg .u64 t; cvta.to.shared.u64 t, %1; cvt.u32.u64 %0, t; }":"=r"(a):"l"(p)); return a;
}
__device__ __forceinline__ uint32_t f2tf(float f){
    uint32_t r; asm("cvt.rn.tf32.f32 %0, %1;" : "=r"(r) : "f"(f)); return r;
}
__device__ __forceinline__ uint32_t lds(uint32_t a){
    uint32_t v; asm volatile("ld.shared.b32 %0, [%1];" : "=r"(v) : "r"(a)); return v;
}
__device__ __forceinline__ void mma_tf32(float* c, uint32_t a0, uint32_t a1,
                                         uint32_t a2, uint32_t a3,
                                         uint32_t b0, uint32_t b1){
    asm volatile("mma.sync.aligned.m16n8k8.row.col.f32.tf32.tf32.f32 "
        "{%0,%1,%2,%3}, {%4,%5,%6,%7}, {%8,%9}, {%0,%1,%2,%3};"
        : "+f"(c[0]),"+f"(c[1]),"+f"(c[2]),"+f"(c[3])
        : "r"(a0),"r"(a1),"r"(a2),"r"(a3),"r"(b0),"r"(b1));
}

// ---------------- prep ----------------
__global__ void prep_kernel(const float* __restrict__ cw){
    int i = blockIdx.x*256 + threadIdx.x;
    if (i < KW*D*D){
        int k = i%KW, c = (i/KW)%D, o = i/(KW*D);
        d_cwT[(k*D+c)*D+o] = cw[i];
    }
}
__global__ void bias_kernel(const float* __restrict__ cw, const float* __restrict__ cb,
                            const float* __restrict__ b1){
    __shared__ float s[128];
    int o = blockIdx.x; float p = 0.f;
    for (int c = threadIdx.x; c < D; c += 128){
        const float* w = cw + ((size_t)o*D+c)*KW;
        p += b1[c]*(w[0]+w[1]+w[2]+w[3]+w[4]);
    }
    s[threadIdx.x] = p; __syncthreads();
    for (int st = 64; st; st >>= 1){
        if (threadIdx.x < st) s[threadIdx.x] += s[threadIdx.x+st];
        __syncthreads();
    }
    if (threadIdx.x == 0) d_biasf[o] = cb[o] + s[0];
}
__global__ void fuse_kernel(const float* __restrict__ W1){
    __shared__ float w1s[8][D];
    int k = blockIdx.x/38, d0 = (blockIdx.x%38)*8, tid = threadIdx.x;
    for (int i = tid; i < 8*D; i += blockDim.x){
        int q = i/D, c = i%D;
        w1s[q][c] = (d0+q < D) ? W1[(size_t)(d0+q)*D+c] : 0.f;
    }
    __syncthreads();
    if (tid < D){
        float a[8];
        #pragma unroll
        for (int q = 0; q < 8; q++) a[q] = 0.f;
        const float* ct = d_cwT + (size_t)k*D*D + tid;
        for (int c = 0; c < D; c++){
            float v = ct[(size_t)c*D];
            #pragma unroll
            for (int q = 0; q < 8; q++) a[q] = fmaf(w1s[q][c], v, a[q]);
        }
        #pragma unroll
        for (int q = 0; q < 8; q++)
            if (d0+q < D) d_Wf[(size_t)(k*D+d0+q)*D + tid] = a[q];
    }
}
// pack: [k][oph][d 304][o' 152], tf32 bits (identical to R5)
__global__ void pack_kernel(){
    int i = blockIdx.x*256 + threadIdx.x;
    if (i >= KW*2*304*152) return;
    int op = i % 152;
    int dd = (i/152) % 304;
    int oph = (i/152/304) % 2;
    int k = i/(152*304*2);
    int o = oph*152 + op;
    float w = (dd < D && o < D) ? d_Wf[(size_t)(k*D+dd)*D + o] : 0.f;
    ((uint32_t*)d_Wpk)[i] = f2tf(w);
}

// ---------------- main ----------------
__device__ __forceinline__ void load_chunk(uint32_t sb, int oph, int c, int tid){
    int k = c/19, dc = c - k*19;
    const float* src = d_Wpk + ((size_t)((k*2 + oph)*304) + dc*16)*152;
    uint32_t dst = sb + OFF_B + (c & 3)*BCHUNK;
    #pragma unroll
    for (int u = 0; u < 3; u++){
        int i = tid + u*256;
        if (i < 608){                       // 16 rows x 152 floats = 608 uint4
            asm volatile("cp.async.cg.shared.global [%0], [%1], 16;"
                         :: "r"(dst + (uint32_t)i*16), "l"(src + i*4) : "memory");
        }
    }
    asm volatile("cp.async.commit_group;" ::: "memory");
}

__global__ void __launch_bounds__(256,1)
main_kernel(const int* __restrict__ tok, const float* __restrict__ mention,
            const float* __restrict__ emb){
    extern __shared__ char sm[];
    const uint32_t sb = s2u(sm);
    const int n = blockIdx.x >> 1, oph = blockIdx.x & 1;
    const int tid = threadIdx.x, wid = tid>>5, lane = tid&31;

    if (tid < L) ((int*)sm)[tid] = tok[n*L + tid];
    // zero pads: cols 300..315 rows 0..127; rows 128..131 full
    for (int i = tid; i < 128*16; i += 256){
        int r = i>>4, w = 300 + (i&15);
        *(uint32_t*)(sm + OFF_G + (uint32_t)(r*GSTR + w)*4) = 0u;
    }
    for (int i = tid; i < 4*GSTR; i += 256)
        *(uint32_t*)(sm + OFF_G + (uint32_t)(128*GSTR + i)*4) = 0u;
    __syncthreads();

    // gather G (fp32 -> tf32 bits)
    {
        const int* stok = (const int*)sm;
        for (int i = tid; i < 128*75; i += 256){
            int r = i/75, q = i - r*75;
            float4 v = __ldg((const float4*)(emb + (size_t)stok[r]*D) + q);
            uint4 t;
            t.x = f2tf(v.x); t.y = f2tf(v.y); t.z = f2tf(v.z); t.w = f2tf(v.w);
            *(uint4*)(sm + OFF_G + (uint32_t)(r*GSTR + q*4)*4) = t;
        }
    }

    float acc[19][4];
    #pragma unroll
    for (int j = 0; j < 19; j++)
        acc[j][0] = acc[j][1] = acc[j][2] = acc[j][3] = 0.f;

    load_chunk(sb, oph, 0, tid);
    load_chunk(sb, oph, 1, tid);

    const int r = lane >> 2, q4 = lane & 3;

    for (int c = 0; c < 95; c++){
        if (c + 2 < 95){
            load_chunk(sb, oph, c + 2, tid);
            asm volatile("cp.async.wait_group 2;" ::: "memory");
        } else if (c + 1 < 95){
            asm volatile("cp.async.wait_group 1;" ::: "memory");
        } else {
            asm volatile("cp.async.wait_group 0;" ::: "memory");
        }
        __syncthreads();    // single barrier per iteration (NB=4, prefetch dist 2)

        const int k = c/19, d0 = (c - k*19)*16;
        uint32_t ga0 = sb + OFF_G + (uint32_t)((wid*16 + r + k)*GSTR + q4 + d0)*4;
        uint32_t bb0 = sb + OFF_B + (c & 3)*BCHUNK + (uint32_t)(q4*BSTR + r)*4;

        #pragma unroll
        for (int ds = 0; ds < 2; ds++){
            uint32_t ga = ga0 + ds*32;
            uint32_t a0 = lds(ga);
            uint32_t a1 = lds(ga + 8*GSTR*4);
            uint32_t a2 = lds(ga + 16);
            uint32_t a3 = lds(ga + 8*GSTR*4 + 16);
            uint32_t bb = bb0 + ds*8*BSTR*4;
            #pragma unroll
            for (int j = 0; j < 19; j++){
                uint32_t b0 = lds(bb + j*32);
                uint32_t b1 = lds(bb + j*32 + 4*BSTR*4);
                mma_tf32(acc[j], a0, a1, a2, a3, b0, b1);
            }
        }
    }

    // ---- maxpool over t (R5 logic verbatim) ----
    float* red = (float*)(sm + OFF_RED);
    __syncthreads();
    int t0 = wid*16 + r, t1 = t0 + 8;
    #pragma unroll
    for (int j = 0; j < 19; j++){
        float m0 = fmaxf(t0 < LT ? acc[j][0] : -3.4e38f,
                         t1 < LT ? acc[j][2] : -3.4e38f);
        float m1 = fmaxf(t0 < LT ? acc[j][1] : -3.4e38f,
                         t1 < LT ? acc[j][3] : -3.4e38f);
        #pragma unroll
        for (int off = 4; off <= 16; off <<= 1){
            m0 = fmaxf(m0, __shfl_xor_sync(0xffffffffu, m0, off));
            m1 = fmaxf(m1, __shfl_xor_sync(0xffffffffu, m1, off));
        }
        if (lane < 4){
            red[wid*152 + j*8 + 2*lane]     = m0;
            red[wid*152 + j*8 + 2*lane + 1] = m1;
        }
    }
    __syncthreads();
    if (tid < 152){
        float m = red[tid];
        #pragma unroll
        for (int w = 1; w < 8; w++) m = fmaxf(m, red[w*152 + tid]);
        int o = oph*152 + tid;
        if (o < D) d_conc[(size_t)n*600 + o] = m + d_biasf[o];
    }
    if (oph == 0)
        for (int i = tid; i < D; i += 256)
            d_conc[(size_t)n*600 + D + i] = mention[(size_t)n*D + i];
}

// ---------------- MLP epilogue: 4 bags per CTA ----------------
__global__ void __launch_bounds__(256,1)
mlp_kernel(const float* __restrict__ W2, const float* __restrict__ b2,
           const float* __restrict__ W3, const float* __restrict__ b3,
           float* __restrict__ out){
    __shared__ float cs[4*600], hs[4*300];
    const int nb = blockIdx.x*4, tid = threadIdx.x;
    for (int i = tid; i < 2400; i += 256) cs[i] = d_conc[(size_t)nb*600 + i];
    __syncthreads();
    for (int o = tid; o < D; o += 256){
        float a0 = b2[o], a1 = a0, a2 = a0, a3 = a0;
        for (int j = 0; j < 600; j++){
            float w = __ldg(&W2[(size_t)j*D + o]);
            a0 = fmaf(cs[j], w, a0);       a1 = fmaf(cs[600+j], w, a1);
            a2 = fmaf(cs[1200+j], w, a2);  a3 = fmaf(cs[1800+j], w, a3);
        }
        hs[o] = tanhf(a0); hs[300+o] = tanhf(a1);
        hs[600+o] = tanhf(a2); hs[900+o] = tanhf(a3);
    }
    __syncthreads();
    for (int o = tid; o < D; o += 256){
        float a0 = b3[o], a1 = a0, a2 = a0, a3 = a0;
        for (int j = 0; j < D; j++){
            float w = __ldg(&W3[(size_t)j*D + o]);
            a0 = fmaf(hs[j], w, a0);      a1 = fmaf(hs[300+j], w, a1);
            a2 = fmaf(hs[600+j], w, a2);  a3 = fmaf(hs[900+j], w, a3);
        }
        out[(size_t)nb*D + o] = a0;       out[(size_t)(nb+1)*D + o] = a1;
        out[(size_t)(nb+2)*D + o] = a2;   out[(size_t)(nb+3)*D + o] = a3;
    }
}

extern "C" void kernel_launch(void* const* d_in, const int* in_sizes, int n_in,
                              void* d_out, int out_size){
    const int*   tok     = (const int*)  d_in[0];
    const float* mention = (const float*)d_in[1];
    const float* emb     = (const float*)d_in[2];
    const float* W1      = (const float*)d_in[3];
    const float* b1      = (const float*)d_in[4];
    const float* conv_w  = (const float*)d_in[5];
    const float* conv_b  = (const float*)d_in[6];
    const float* W2      = (const float*)d_in[7];
    const float* b2      = (const float*)d_in[8];
    const float* W3      = (const float*)d_in[9];
    const float* b3      = (const float*)d_in[10];
    float* out = (float*)d_out;

    cudaFuncSetAttribute(main_kernel, cudaFuncAttributeMaxDynamicSharedMemorySize, SMEM_T);
    prep_kernel<<<(KW*D*D + 255)/256, 256>>>(conv_w);
    bias_kernel<<<D, 128>>>(conv_w, conv_b, b1);
    fuse_kernel<<<KW*38, 320>>>(W1);
    pack_kernel<<<(KW*2*304*152 + 255)/256, 256>>>();
    main_kernel<<<2048, 256, SMEM_T>>>(tok, mention, emb);
    mlp_kernel<<<256, 256>>>(W2, b2, W3, b3, out);
}

// round 8
// speedup vs baseline: 1.5405x; 1.5405x over previous
#include <cuda_runtime.h>
#include <cuda_fp16.h>
#include <cstdint>

#define D 300
#define L 128
#define LT 124
#define KW 5

#define GH    312                          // G row stride in halves (624 B)
#define BCH   4864                         // B chunk bytes: 152 o-rows x 16 k halves
#define OFF_G   512
#define OFF_B   (OFF_G + 132*GH*2)         // 512 + 82368 = 82880
#define OFF_RED (OFF_B + 4*BCH)            // 102336
#define SMEM_T  (OFF_RED + 8*152*4)        // 107200

__device__ float d_cwT[KW*D*D];
__device__ float d_Wf[KW*D*D];
__device__ float d_biasf[D];
__device__ __align__(16) __half d_WpkH[KW*2*19*152*16];   // [k][oph][dc][o'][kk]
__device__ float d_conc[1024*600];

// ---------------- helpers ----------------
__device__ __forceinline__ uint32_t s2u(const void* p){
    uint32_t a; asm("{ .reg .u64 t; cvta.to.shared.u64 t, %1; cvt.u32.u64 %0, t; }":"=r"(a):"l"(p)); return a;
}
__device__ __forceinline__ uint32_t lds(uint32_t a){
    uint32_t v; asm volatile("ld.shared.b32 %0, [%1];" : "=r"(v) : "r"(a)); return v;
}
__device__ __forceinline__ void mma_f16(float* c, uint32_t a0, uint32_t a1,
                                        uint32_t a2, uint32_t a3,
                                        uint32_t b0, uint32_t b1){
    asm volatile("mma.sync.aligned.m16n8k16.row.col.f32.f16.f16.f32 "
        "{%0,%1,%2,%3}, {%4,%5,%6,%7}, {%8,%9}, {%0,%1,%2,%3};"
        : "+f"(c[0]),"+f"(c[1]),"+f"(c[2]),"+f"(c[3])
        : "r"(a0),"r"(a1),"r"(a2),"r"(a3),"r"(b0),"r"(b1));
}

// ---------------- prep ----------------
__global__ void prep_kernel(const float* __restrict__ cw){
    int i = blockIdx.x*256 + threadIdx.x;
    if (i < KW*D*D){
        int k = i%KW, c = (i/KW)%D, o = i/(KW*D);
        d_cwT[(k*D+c)*D+o] = cw[i];
    }
}
__global__ void bias_kernel(const float* __restrict__ cw, const float* __restrict__ cb,
                            const float* __restrict__ b1){
    __shared__ float s[128];
    int o = blockIdx.x; float p = 0.f;
    for (int c = threadIdx.x; c < D; c += 128){
        const float* w = cw + ((size_t)o*D+c)*KW;
        p += b1[c]*(w[0]+w[1]+w[2]+w[3]+w[4]);
    }
    s[threadIdx.x] = p; __syncthreads();
    for (int st = 64; st; st >>= 1){
        if (threadIdx.x < st) s[threadIdx.x] += s[threadIdx.x+st];
        __syncthreads();
    }
    if (threadIdx.x == 0) d_biasf[o] = cb[o] + s[0];
}
__global__ void fuse_kernel(const float* __restrict__ W1){
    __shared__ float w1s[8][D];
    int k = blockIdx.x/38, d0 = (blockIdx.x%38)*8, tid = threadIdx.x;
    for (int i = tid; i < 8*D; i += blockDim.x){
        int q = i/D, c = i%D;
        w1s[q][c] = (d0+q < D) ? W1[(size_t)(d0+q)*D+c] : 0.f;
    }
    __syncthreads();
    if (tid < D){
        float a[8];
        #pragma unroll
        for (int q = 0; q < 8; q++) a[q] = 0.f;
        const float* ct = d_cwT + (size_t)k*D*D + tid;
        for (int c = 0; c < D; c++){
            float v = ct[(size_t)c*D];
            #pragma unroll
            for (int q = 0; q < 8; q++) a[q] = fmaf(w1s[q][c], v, a[q]);
        }
        #pragma unroll
        for (int q = 0; q < 8; q++)
            if (d0+q < D) d_Wf[(size_t)(k*D+d0+q)*D + tid] = a[q];
    }
}
// pack: fp16 [k][oph][dc 19][o' 152][kk 16]
__global__ void pack_kernel(){
    int i = blockIdx.x*256 + threadIdx.x;
    if (i >= KW*2*19*152*16) return;
    int kk  = i % 16;
    int o   = (i/16) % 152;
    int dc  = (i/16/152) % 19;
    int oph = (i/(16*152*19)) % 2;
    int k   = i/(16*152*19*2);
    int dd = dc*16 + kk, oo = oph*152 + o;
    float w = (dd < D && oo < D) ? d_Wf[(size_t)(k*D+dd)*D + oo] : 0.f;
    d_WpkH[i] = __float2half_rn(w);
}

// ---------------- main ----------------
__device__ __forceinline__ void load_chunk(uint32_t sb, int oph, int c, int tid){
    int k = c/19, dc = c - k*19;
    const __half* src = d_WpkH + ((size_t)((k*2 + oph)*19 + dc))*2432;
    uint32_t dst = sb + OFF_B + (c & 3)*BCH;
    #pragma unroll
    for (int u = 0; u < 2; u++){
        int i = tid + u*256;
        if (i < 304){
            asm volatile("cp.async.cg.shared.global [%0], [%1], 16;"
                         :: "r"(dst + (uint32_t)i*16), "l"(src + i*8) : "memory");
        }
    }
    asm volatile("cp.async.commit_group;" ::: "memory");
}

__global__ void __launch_bounds__(256,2)
main_kernel(const int* __restrict__ tok, const float* __restrict__ mention,
            const float* __restrict__ emb){
    extern __shared__ char sm[];
    const uint32_t sb = s2u(sm);
    const int n = blockIdx.x, tid = threadIdx.x, wid = tid>>5, lane = tid&31;

    if (tid < L) ((int*)sm)[tid] = tok[n*L + tid];
    // zero pads: rows 0..127 halves 300..311 (6 words), rows 128..131 full
    for (int i = tid; i < 128*6; i += 256){
        int r = i/6, w = i - r*6;
        *(uint32_t*)(sm + OFF_G + (uint32_t)(r*156 + 150 + w)*4) = 0u;
    }
    for (int i = tid; i < 4*156; i += 256)
        *(uint32_t*)(sm + OFF_G + (uint32_t)(128*156 + i)*4) = 0u;
    __syncthreads();

    // gather G (fp32 -> fp16)
    {
        const int* stok = (const int*)sm;
        for (int i = tid; i < 128*75; i += 256){
            int r = i/75, q = i - r*75;
            float4 v = __ldg((const float4*)(emb + (size_t)stok[r]*D) + q);
            uint2 t;
            __half2 h01 = __floats2half2_rn(v.x, v.y);
            __half2 h23 = __floats2half2_rn(v.z, v.w);
            t.x = *(uint32_t*)&h01; t.y = *(uint32_t*)&h23;
            *(uint2*)(sm + OFF_G + (uint32_t)r*624 + (uint32_t)q*8) = t;
        }
    }

    float* red = (float*)(sm + OFF_RED);
    const int r = lane >> 2, q4 = lane & 3;

    for (int oph = 0; oph < 2; oph++){
        float acc[19][4];
        #pragma unroll
        for (int j = 0; j < 19; j++)
            acc[j][0] = acc[j][1] = acc[j][2] = acc[j][3] = 0.f;

        load_chunk(sb, oph, 0, tid);
        load_chunk(sb, oph, 1, tid);

        for (int c = 0; c < 95; c++){
            if (c + 2 < 95){
                load_chunk(sb, oph, c + 2, tid);
                asm volatile("cp.async.wait_group 2;" ::: "memory");
            } else if (c + 1 < 95){
                asm volatile("cp.async.wait_group 1;" ::: "memory");
            } else {
                asm volatile("cp.async.wait_group 0;" ::: "memory");
            }
            __syncthreads();

            const int k = c/19, d0 = (c - k*19)*16;
            uint32_t ga = sb + OFF_G + (uint32_t)(wid*16 + r + k)*624
                                     + (uint32_t)(d0 + 2*q4)*2;
            uint32_t a0 = lds(ga);
            uint32_t a1 = lds(ga + 8*624);
            uint32_t a2 = lds(ga + 16);
            uint32_t a3 = lds(ga + 8*624 + 16);

            uint32_t bb = sb + OFF_B + (c & 3)*BCH + (uint32_t)(r*32 + q4*4);
            #pragma unroll
            for (int j = 0; j < 19; j++){
                uint32_t b0 = lds(bb + j*256);
                uint32_t b1 = lds(bb + j*256 + 16);
                mma_f16(acc[j], a0, a1, a2, a3, b0, b1);
            }
        }

        // ---- maxpool over t (fragment layout identical to tf32 path) ----
        __syncthreads();
        int t0 = wid*16 + r, t1 = t0 + 8;
        #pragma unroll
        for (int j = 0; j < 19; j++){
            float m0 = fmaxf(t0 < LT ? acc[j][0] : -3.4e38f,
                             t1 < LT ? acc[j][2] : -3.4e38f);
            float m1 = fmaxf(t0 < LT ? acc[j][1] : -3.4e38f,
                             t1 < LT ? acc[j][3] : -3.4e38f);
            #pragma unroll
            for (int off = 4; off <= 16; off <<= 1){
                m0 = fmaxf(m0, __shfl_xor_sync(0xffffffffu, m0, off));
                m1 = fmaxf(m1, __shfl_xor_sync(0xffffffffu, m1, off));
            }
            if (lane < 4){
                red[wid*152 + j*8 + 2*lane]     = m0;
                red[wid*152 + j*8 + 2*lane + 1] = m1;
            }
        }
        __syncthreads();
        if (tid < 152){
            float m = red[tid];
            #pragma unroll
            for (int w = 1; w < 8; w++) m = fmaxf(m, red[w*152 + tid]);
            int o = oph*152 + tid;
            if (o < D) d_conc[(size_t)n*600 + o] = m + d_biasf[o];
        }
        __syncthreads();
    }

    for (int i = tid; i < D; i += 256)
        d_conc[(size_t)n*600 + D + i] = mention[(size_t)n*D + i];
}

// ---------------- MLP epilogue: 4 bags per CTA ----------------
__global__ void __launch_bounds__(256,1)
mlp_kernel(const float* __restrict__ W2, const float* __restrict__ b2,
           const float* __restrict__ W3, const float* __restrict__ b3,
           float* __restrict__ out){
    __shared__ float cs[4*600], hs[4*300];
    const int nb = blockIdx.x*4, tid = threadIdx.x;
    for (int i = tid; i < 2400; i += 256) cs[i] = d_conc[(size_t)nb*600 + i];
    __syncthreads();
    for (int o = tid; o < D; o += 256){
        float a0 = b2[o], a1 = a0, a2 = a0, a3 = a0;
        for (int j = 0; j < 600; j++){
            float w = __ldg(&W2[(size_t)j*D + o]);
            a0 = fmaf(cs[j], w, a0);       a1 = fmaf(cs[600+j], w, a1);
            a2 = fmaf(cs[1200+j], w, a2);  a3 = fmaf(cs[1800+j], w, a3);
        }
        hs[o] = tanhf(a0); hs[300+o] = tanhf(a1);
        hs[600+o] = tanhf(a2); hs[900+o] = tanhf(a3);
    }
    __syncthreads();
    for (int o = tid; o < D; o += 256){
        float a0 = b3[o], a1 = a0, a2 = a0, a3 = a0;
        for (int j = 0; j < D; j++){
            float w = __ldg(&W3[(size_t)j*D + o]);
            a0 = fmaf(hs[j], w, a0);      a1 = fmaf(hs[300+j], w, a1);
            a2 = fmaf(hs[600+j], w, a2);  a3 = fmaf(hs[900+j], w, a3);
        }
        out[(size_t)nb*D + o] = a0;       out[(size_t)(nb+1)*D + o] = a1;
        out[(size_t)(nb+2)*D + o] = a2;   out[(size_t)(nb+3)*D + o] = a3;
    }
}

extern "C" void kernel_launch(void* const* d_in, const int* in_sizes, int n_in,
                              void* d_out, int out_size){
    const int*   tok     = (const int*)  d_in[0];
    const float* mention = (const float*)d_in[1];
    const float* emb     = (const float*)d_in[2];
    const float* W1      = (const float*)d_in[3];
    const float* b1      = (const float*)d_in[4];
    const float* conv_w  = (const float*)d_in[5];
    const float* conv_b  = (const float*)d_in[6];
    const float* W2      = (const float*)d_in[7];
    const float* b2      = (const float*)d_in[8];
    const float* W3      = (const float*)d_in[9];
    const float* b3      = (const float*)d_in[10];
    float* out = (float*)d_out;

    cudaFuncSetAttribute(main_kernel, cudaFuncAttributeMaxDynamicSharedMemorySize, SMEM_T);
    prep_kernel<<<(KW*D*D + 255)/256, 256>>>(conv_w);
    bias_kernel<<<D, 128>>>(conv_w, conv_b, b1);
    fuse_kernel<<<KW*38, 320>>>(W1);
    pack_kernel<<<(KW*2*19*152*16 + 255)/256, 256>>>();
    main_kernel<<<1024, 256, SMEM_T>>>(tok, mention, emb);
    mlp_kernel<<<256, 256>>>(W2, b2, W3, b3, out);
}

// round 9
// speedup vs baseline: 2.0989x; 1.3625x over previous
#include <cuda_runtime.h>
#include <cuda_fp16.h>
#include <cstdint>

#define D 300
#define L 128
#define LT 124
#define KW 5

#define BCH   4864                         // one B chunk: 19 j x 32 lanes x 8 B
#define OFF_G   512
#define OFF_B   (OFF_G + 132*624)          // 82880
#define SMEM_T  (OFF_B + 6*BCH)            // 112064

__device__ float d_cwT[KW*D*D];
__device__ float d_Wf[KW*D*D];
__device__ float d_biasf[D];
__device__ __align__(16) __half d_WpkH[KW*2*19*19*32*4];   // fragment-order B
__device__ float d_conc[1024*600];

// ---------------- helpers ----------------
__device__ __forceinline__ uint32_t s2u(const void* p){
    uint32_t a; asm("{ .reg .u64 t; cvta.to.shared.u64 t, %1; cvt.u32.u64 %0, t; }":"=r"(a):"l"(p)); return a;
}
__device__ __forceinline__ void mma_f16(float* c, uint32_t a0, uint32_t a1,
                                        uint32_t a2, uint32_t a3,
                                        uint32_t b0, uint32_t b1){
    asm volatile("mma.sync.aligned.m16n8k16.row.col.f32.f16.f16.f32 "
        "{%0,%1,%2,%3}, {%4,%5,%6,%7}, {%8,%9}, {%0,%1,%2,%3};"
        : "+f"(c[0]),"+f"(c[1]),"+f"(c[2]),"+f"(c[3])
        : "r"(a0),"r"(a1),"r"(a2),"r"(a3),"r"(b0),"r"(b1));
}

// ---------------- prep ----------------
__global__ void prep_kernel(const float* __restrict__ cw){
    int i = blockIdx.x*256 + threadIdx.x;
    if (i < KW*D*D){
        int k = i%KW, c = (i/KW)%D, o = i/(KW*D);
        d_cwT[(k*D+c)*D+o] = cw[i];
    }
}
__global__ void bias_kernel(const float* __restrict__ cw, const float* __restrict__ cb,
                            const float* __restrict__ b1){
    __shared__ float s[128];
    int o = blockIdx.x; float p = 0.f;
    for (int c = threadIdx.x; c < D; c += 128){
        const float* w = cw + ((size_t)o*D+c)*KW;
        p += b1[c]*(w[0]+w[1]+w[2]+w[3]+w[4]);
    }
    s[threadIdx.x] = p; __syncthreads();
    for (int st = 64; st; st >>= 1){
        if (threadIdx.x < st) s[threadIdx.x] += s[threadIdx.x+st];
        __syncthreads();
    }
    if (threadIdx.x == 0) d_biasf[o] = cb[o] + s[0];
}
__global__ void fuse_kernel(const float* __restrict__ W1){
    __shared__ float w1s[8][D];
    int k = blockIdx.x/38, d0 = (blockIdx.x%38)*8, tid = threadIdx.x;
    for (int i = tid; i < 8*D; i += blockDim.x){
        int q = i/D, c = i%D;
        w1s[q][c] = (d0+q < D) ? W1[(size_t)(d0+q)*D+c] : 0.f;
    }
    __syncthreads();
    if (tid < D){
        float a[8];
        #pragma unroll
        for (int q = 0; q < 8; q++) a[q] = 0.f;
        const float* ct = d_cwT + (size_t)k*D*D + tid;
        for (int c = 0; c < D; c++){
            float v = ct[(size_t)c*D];
            #pragma unroll
            for (int q = 0; q < 8; q++) a[q] = fmaf(w1s[q][c], v, a[q]);
        }
        #pragma unroll
        for (int q = 0; q < 8; q++)
            if (d0+q < D) d_Wf[(size_t)(k*D+d0+q)*D + tid] = a[q];
    }
}
// pack B in mma fragment order: [k][oph][dc][j][lane][h], h: {k2q4,k2q4+1,k2q4+8,k2q4+9}
__global__ void pack_kernel(){
    int i = blockIdx.x*256 + threadIdx.x;
    if (i >= KW*2*19*19*32*4) return;
    int h    = i & 3;
    int lane = (i >> 2) & 31;
    int j    = (i >> 7) % 19;
    int dc   = (i / (128*19)) % 19;
    int oph  = (i / (128*19*19)) % 2;
    int k    = i / (128*19*19*2);
    int r = lane >> 2, q4 = lane & 3;
    int kk = 2*q4 + (h & 1) + ((h >> 1) << 3);
    int dd = dc*16 + kk;
    int oo = oph*152 + j*8 + r;
    float w = (dd < D && oo < D) ? d_Wf[(size_t)(k*D+dd)*D + oo] : 0.f;
    d_WpkH[i] = __float2half_rn(w);
}

// ---------------- main ----------------
__device__ __forceinline__ void load_chunk(uint32_t sb, int oph, int c, int tid){
    int k = c/19, dc = c - k*19;
    const __half* src = d_WpkH + ((size_t)((k*2 + oph)*19 + dc))*2432;
    uint32_t dst = sb + OFF_B + (uint32_t)(c % 6)*BCH;
    #pragma unroll
    for (int u = 0; u < 2; u++){
        int i = tid + u*256;
        if (i < 304){
            asm volatile("cp.async.cg.shared.global [%0], [%1], 16;"
                         :: "r"(dst + (uint32_t)i*16), "l"(src + i*8) : "memory");
        }
    }
    asm volatile("cp.async.commit_group;" ::: "memory");
}

__device__ __forceinline__ void do_chunk(uint32_t sb, uint32_t gbase, int c,
                                         float (*acc)[4], int lane){
    const int k = c/19, dcb = (c - k*19)*32;         // byte offset of 16 halves
    uint32_t ga = gbase + (uint32_t)(k*624 + dcb);
    uint32_t a0, a1, a2, a3;
    asm volatile("ldmatrix.sync.aligned.m8n8.x4.shared.b16 {%0,%1,%2,%3}, [%4];"
                 : "=r"(a0),"=r"(a1),"=r"(a2),"=r"(a3) : "r"(ga));
    uint32_t bb = sb + OFF_B + (uint32_t)(c % 6)*BCH + (uint32_t)lane*8;
    #pragma unroll
    for (int j = 0; j < 19; j++){
        uint32_t b0, b1;
        asm volatile("ld.shared.v2.b32 {%0,%1}, [%2];"
                     : "=r"(b0), "=r"(b1) : "r"(bb + (uint32_t)j*256));
        mma_f16(acc[j], a0, a1, a2, a3, b0, b1);
    }
}

__global__ void __launch_bounds__(256,2)
main_kernel(const int* __restrict__ tok, const float* __restrict__ mention,
            const float* __restrict__ emb){
    extern __shared__ char sm[];
    const uint32_t sb = s2u(sm);
    const int n = blockIdx.x, tid = threadIdx.x, wid = tid>>5, lane = tid&31;

    if (tid < L) ((int*)sm)[tid] = tok[n*L + tid];
    // zero pads: rows 0..127 halves 300..311 (6 words), rows 128..131 full
    for (int i = tid; i < 128*6; i += 256){
        int r = i/6, w = i - r*6;
        *(uint32_t*)(sm + OFF_G + (uint32_t)(r*156 + 150 + w)*4) = 0u;
    }
    for (int i = tid; i < 4*156; i += 256)
        *(uint32_t*)(sm + OFF_G + (uint32_t)(128*156 + i)*4) = 0u;
    __syncthreads();

    // gather G (fp32 -> fp16), row stride 624 B
    {
        const int* stok = (const int*)sm;
        for (int i = tid; i < 128*75; i += 256){
            int r = i/75, q = i - r*75;
            float4 v = __ldg((const float4*)(emb + (size_t)stok[r]*D) + q);
            uint2 t;
            __half2 h01 = __floats2half2_rn(v.x, v.y);
            __half2 h23 = __floats2half2_rn(v.z, v.w);
            t.x = *(uint32_t*)&h01; t.y = *(uint32_t*)&h23;
            *(uint2*)(sm + OFF_G + (uint32_t)r*624 + (uint32_t)q*8) = t;
        }
    }

    const int r = lane >> 2;
    const uint32_t gbase = sb + OFF_G + (uint32_t)(wid*16 + (lane & 15))*624
                                      + (uint32_t)((lane >> 4) << 4);
    float* red = (float*)(sm + OFF_B);      // overlays B ring (quiescent at epilogue)

    for (int oph = 0; oph < 2; oph++){
        float acc[19][4];
        #pragma unroll
        for (int j = 0; j < 19; j++)
            acc[j][0] = acc[j][1] = acc[j][2] = acc[j][3] = 0.f;

        // prologue: chunks 0..3
        load_chunk(sb, oph, 0, tid);
        load_chunk(sb, oph, 1, tid);
        load_chunk(sb, oph, 2, tid);
        load_chunk(sb, oph, 3, tid);

        for (int p = 0; p < 47; p++){
            if (p < 46) asm volatile("cp.async.wait_group 2;" ::: "memory");
            else        asm volatile("cp.async.wait_group 1;" ::: "memory");
            __syncthreads();
            if (p < 45){
                load_chunk(sb, oph, 2*p + 4, tid);
                load_chunk(sb, oph, 2*p + 5, tid);
            } else if (p == 45){
                load_chunk(sb, oph, 94, tid);
            }
            do_chunk(sb, gbase, 2*p,     acc, lane);
            do_chunk(sb, gbase, 2*p + 1, acc, lane);
        }
        // tail chunk 94
        asm volatile("cp.async.wait_group 0;" ::: "memory");
        __syncthreads();
        do_chunk(sb, gbase, 94, acc, lane);

        // ---- maxpool over t (fragment layout unchanged) ----
        __syncthreads();
        int t0 = wid*16 + r, t1 = t0 + 8;
        #pragma unroll
        for (int j = 0; j < 19; j++){
            float m0 = fmaxf(t0 < LT ? acc[j][0] : -3.4e38f,
                             t1 < LT ? acc[j][2] : -3.4e38f);
            float m1 = fmaxf(t0 < LT ? acc[j][1] : -3.4e38f,
                             t1 < LT ? acc[j][3] : -3.4e38f);
            #pragma unroll
            for (int off = 4; off <= 16; off <<= 1){
                m0 = fmaxf(m0, __shfl_xor_sync(0xffffffffu, m0, off));
                m1 = fmaxf(m1, __shfl_xor_sync(0xffffffffu, m1, off));
            }
            if (lane < 4){
                red[wid*152 + j*8 + 2*lane]     = m0;
                red[wid*152 + j*8 + 2*lane + 1] = m1;
            }
        }
        __syncthreads();
        if (tid < 152){
            float m = red[tid];
            #pragma unroll
            for (int w = 1; w < 8; w++) m = fmaxf(m, red[w*152 + tid]);
            int o = oph*152 + tid;
            if (o < D) d_conc[(size_t)n*600 + o] = m + d_biasf[o];
        }
        __syncthreads();   // red fully consumed before next oph's cp.async overwrites it
    }

    for (int i = tid; i < D; i += 256)
        d_conc[(size_t)n*600 + D + i] = mention[(size_t)n*D + i];
}

// ---------------- MLP epilogue: 4 bags per CTA ----------------
__global__ void __launch_bounds__(256,1)
mlp_kernel(const float* __restrict__ W2, const float* __restrict__ b2,
           const float* __restrict__ W3, const float* __restrict__ b3,
           float* __restrict__ out){
    __shared__ float cs[4*600], hs[4*300];
    const int nb = blockIdx.x*4, tid = threadIdx.x;
    for (int i = tid; i < 2400; i += 256) cs[i] = d_conc[(size_t)nb*600 + i];
    __syncthreads();
    for (int o = tid; o < D; o += 256){
        float a0 = b2[o], a1 = a0, a2 = a0, a3 = a0;
        for (int j = 0; j < 600; j++){
            float w = __ldg(&W2[(size_t)j*D + o]);
            a0 = fmaf(cs[j], w, a0);       a1 = fmaf(cs[600+j], w, a1);
            a2 = fmaf(cs[1200+j], w, a2);  a3 = fmaf(cs[1800+j], w, a3);
        }
        hs[o] = tanhf(a0); hs[300+o] = tanhf(a1);
        hs[600+o] = tanhf(a2); hs[900+o] = tanhf(a3);
    }
    __syncthreads();
    for (int o = tid; o < D; o += 256){
        float a0 = b3[o], a1 = a0, a2 = a0, a3 = a0;
        for (int j = 0; j < D; j++){
            float w = __ldg(&W3[(size_t)j*D + o]);
            a0 = fmaf(hs[j], w, a0);      a1 = fmaf(hs[300+j], w, a1);
            a2 = fmaf(hs[600+j], w, a2);  a3 = fmaf(hs[900+j], w, a3);
        }
        out[(size_t)nb*D + o] = a0;       out[(size_t)(nb+1)*D + o] = a1;
        out[(size_t)(nb+2)*D + o] = a2;   out[(size_t)(nb+3)*D + o] = a3;
    }
}

extern "C" void kernel_launch(void* const* d_in, const int* in_sizes, int n_in,
                              void* d_out, int out_size){
    const int*   tok     = (const int*)  d_in[0];
    const float* mention = (const float*)d_in[1];
    const float* emb     = (const float*)d_in[2];
    const float* W1      = (const float*)d_in[3];
    const float* b1      = (const float*)d_in[4];
    const float* conv_w  = (const float*)d_in[5];
    const float* conv_b  = (const float*)d_in[6];
    const float* W2      = (const float*)d_in[7];
    const float* b2      = (const float*)d_in[8];
    const float* W3      = (const float*)d_in[9];
    const float* b3      = (const float*)d_in[10];
    float* out = (float*)d_out;

    cudaFuncSetAttribute(main_kernel, cudaFuncAttributeMaxDynamicSharedMemorySize, SMEM_T);
    prep_kernel<<<(KW*D*D + 255)/256, 256>>>(conv_w);
    bias_kernel<<<D, 128>>>(conv_w, conv_b, b1);
    fuse_kernel<<<KW*38, 320>>>(W1);
    pack_kernel<<<(KW*2*19*19*32*4 + 255)/256, 256>>>();
    main_kernel<<<1024, 256, SMEM_T>>>(tok, mention, emb);
    mlp_kernel<<<256, 256>>>(W2, b2, W3, b3, out);
}